// round 1
// baseline (speedup 1.0000x reference)
#include <cuda_runtime.h>
#include <cuda_bf16.h>

#define NN   20000
#define DD   8
#define KK   9          // D+1 children per node
#define IN_F 64
#define HID  128
#define OUT  64
#define EE   100000
#define MTOT (NN * KK)  // 180000
#define EPS  1e-5f

// ---------------- scratch (device globals; no runtime allocation) ----------
__device__ float  g_xW1[NN * HID];            // x @ W1            (10.24 MB)
__device__ float  g_z1[(size_t)MTOT * HID];   // pre-BN layer-1    (92.16 MB)
__device__ float  g_z2[NN * OUT];             // pre-BN layer-2    (5.12 MB)
__device__ float  g_s1[2 * HID];              // col sum / sumsq (layer 1)
__device__ float  g_s2[2 * OUT];              // col sum / sumsq (layer 2)
__device__ float  g_bn1[2 * HID];             // scale / shift
__device__ float  g_bn2[2 * OUT];
__device__ double g_loss;

// ---------------- K0: zero per-launch accumulators -------------------------
__global__ void k_init() {
    int t = threadIdx.x;
    if (t < 2 * HID) g_s1[t] = 0.f;
    if (t < 2 * OUT) g_s2[t] = 0.f;
    if (t == 0) g_loss = 0.0;
}

// ---------------- K1: xW1 = x @ W1  (b1 dropped: cancels in BN) ------------
__global__ void k_xw1(const float* __restrict__ x, const float* __restrict__ W1) {
    int t = threadIdx.x;            // column j in [0,128)
    float w[IN_F];
#pragma unroll
    for (int i = 0; i < IN_F; i++) w[i] = W1[i * HID + t];

    __shared__ __align__(16) float xs[4 * IN_F];
    for (int r0 = blockIdx.x * 4; r0 < NN; r0 += gridDim.x * 4) {
        __syncthreads();
        for (int i = t; i < 4 * IN_F; i += 128) xs[i] = x[r0 * IN_F + i];
        __syncthreads();
#pragma unroll
        for (int r = 0; r < 4; r++) {
            const float4* a4 = (const float4*)(xs + r * IN_F);
            float acc = 0.f;
#pragma unroll
            for (int ff = 0; ff < 16; ff++) {
                float4 a = a4[ff];
                acc = fmaf(a.x, w[4 * ff + 0], acc);
                acc = fmaf(a.y, w[4 * ff + 1], acc);
                acc = fmaf(a.z, w[4 * ff + 2], acc);
                acc = fmaf(a.w, w[4 * ff + 3], acc);
            }
            g_xW1[(r0 + r) * HID + t] = acc;
        }
    }
}

// ---------------- K2: level-1 masked mean over grandchildren --------------
// z1[m] = mean_{valid kk} xW1[gc[m][kk]] ; also column sums for BN1 stats.
__global__ void k_gather(const float* __restrict__ node_ts,
                         const int*   __restrict__ nidx,
                         const float* __restrict__ nts) {
    __shared__ int   sg[4][12];
    __shared__ float rcp[16];
    int t = threadIdx.x;            // column j in [0,128)
    if (t < 16) rcp[t] = (t > 0) ? 1.0f / (float)t : 0.f;

    float ssum = 0.f, ssq = 0.f;
    for (int m0 = blockIdx.x * 4; m0 < MTOT; m0 += gridDim.x * 4) {
        __syncthreads();
        if (t < 36) {
            int r = t / 9, kk = t - r * 9;
            int m = m0 + r;
            int g = -1;
            if (m < MTOT) {
                int n = m / 9, kc = m - n * 9;
                int ci; float cts;
                if (kc < DD) { ci = nidx[n * DD + kc]; cts = nts[n * DD + kc]; }
                else         { ci = n;                 cts = node_ts[n]; }
                if (kk < DD) g = (nts[ci * DD + kk] <= cts) ? nidx[ci * DD + kk] : -1;
                else         g = ci;
            }
            sg[r][kk] = g;
        }
        __syncthreads();
#pragma unroll
        for (int r = 0; r < 4; r++) {
            int m = m0 + r;
            if (m >= MTOT) break;
            float acc = 0.f; int cnt = 0;
#pragma unroll
            for (int kk = 0; kk < KK; kk++) {
                int g = sg[r][kk];
                if (g >= 0) { acc += g_xW1[g * HID + t]; cnt++; }
            }
            float z = acc * rcp[cnt];
            g_z1[(size_t)m * HID + t] = z;
            ssum += z; ssq += z * z;
        }
    }
    atomicAdd(&g_s1[t], ssum);
    atomicAdd(&g_s1[HID + t], ssq);
}

// ---------------- K3: BN1 scale/shift --------------------------------------
__global__ void k_bn1(const float* __restrict__ g1, const float* __restrict__ be1) {
    int j = threadIdx.x;
    float inv = 1.0f / (float)MTOT;
    float mean = g_s1[j] * inv;
    float var  = g_s1[HID + j] * inv - mean * mean;
    float sc   = g1[j] * rsqrtf(var + EPS);
    g_bn1[j] = sc;
    g_bn1[HID + j] = be1[j] - mean * sc;
}

// ---------------- K4: BN1+ReLU, level-2 masked mean, GEMM2 -----------------
__global__ void k_layer2(const float* __restrict__ node_ts,
                         const float* __restrict__ nts,
                         const float* __restrict__ W2) {
    int t = threadIdx.x;            // phase A: column j; phase B: (o = t&63, h = t>>6)
    int o = t & 63, h = t >> 6;
    float w[64];
#pragma unroll
    for (int i = 0; i < 64; i++) w[i] = W2[(h * 64 + i) * OUT + o];

    float sc = g_bn1[t], sh = g_bn1[HID + t];
    __shared__ __align__(16) float agg_s[HID];
    __shared__ float bs[HID];
    __shared__ float rcp[16];
    if (t < 16) rcp[t] = (t > 0) ? 1.0f / (float)t : 0.f;

    float s2 = 0.f, q2 = 0.f;
    for (int n = blockIdx.x; n < NN; n += gridDim.x) {
        __syncthreads();
        float tsn = node_ts[n];
        float acc = 0.f; int cnt = 0;
#pragma unroll
        for (int kc = 0; kc < KK; kc++) {
            bool v = (kc < DD) ? (nts[n * DD + kc] <= tsn) : true;
            if (v) {
                float z = g_z1[(size_t)(n * KK + kc) * HID + t];
                acc += fmaxf(fmaf(z, sc, sh), 0.f);
                cnt++;
            }
        }
        agg_s[t] = acc * rcp[cnt];
        __syncthreads();
        float a2 = 0.f;
        const float4* a4 = (const float4*)(agg_s + 64 * h);
#pragma unroll
        for (int ff = 0; ff < 16; ff++) {
            float4 a = a4[ff];
            a2 = fmaf(a.x, w[4 * ff + 0], a2);
            a2 = fmaf(a.y, w[4 * ff + 1], a2);
            a2 = fmaf(a.z, w[4 * ff + 2], a2);
            a2 = fmaf(a.w, w[4 * ff + 3], a2);
        }
        bs[t] = a2;
        __syncthreads();
        if (t < 64) {
            float z2 = bs[t] + bs[t + 64];
            g_z2[n * OUT + t] = z2;
            s2 += z2; q2 += z2 * z2;
        }
    }
    if (t < 64) {
        atomicAdd(&g_s2[t], s2);
        atomicAdd(&g_s2[OUT + t], q2);
    }
}

// ---------------- K5: BN2 scale/shift --------------------------------------
__global__ void k_bn2(const float* __restrict__ g2, const float* __restrict__ be2) {
    int j = threadIdx.x;
    float inv = 1.0f / (float)NN;
    float mean = g_s2[j] * inv;
    float var  = g_s2[OUT + j] * inv - mean * mean;
    float sc   = g2[j] * rsqrtf(var + EPS);
    g_bn2[j] = sc;
    g_bn2[OUT + j] = be2[j] - mean * sc;
}

// ---------------- K6: Hadamard decoder + BCE reduction ---------------------
__global__ void k_dec(const int* __restrict__ target, const int* __restrict__ negp,
                      const float* __restrict__ Wd, const float* __restrict__ bd) {
    int t = threadIdx.x, lane = t & 31, w = t >> 5;
    int gw = blockIdx.x * 8 + w;
    int nw = gridDim.x * 8;

    float sca = g_bn2[lane],      sha = g_bn2[64 + lane];
    float scb = g_bn2[lane + 32], shb = g_bn2[96 + lane];
    float wda = Wd[lane], wdb = Wd[lane + 32];
    float bdv = bd[0];

    float acc = 0.f;
    for (int p = gw; p < 2 * EE; p += nw) {
        int u, v; float y;
        if (p < EE) { u = target[p]; v = target[EE + p]; y = 1.f; }
        else        { u = negp[p - EE]; v = negp[p];     y = 0.f; }
        float eu1 = fmaxf(fmaf(g_z2[u * 64 + lane],      sca, sha), 0.f);
        float ev1 = fmaxf(fmaf(g_z2[v * 64 + lane],      sca, sha), 0.f);
        float eu2 = fmaxf(fmaf(g_z2[u * 64 + 32 + lane], scb, shb), 0.f);
        float ev2 = fmaxf(fmaf(g_z2[v * 64 + 32 + lane], scb, shb), 0.f);
        float d = eu1 * ev1 * wda + eu2 * ev2 * wdb;
#pragma unroll
        for (int s = 16; s > 0; s >>= 1) d += __shfl_xor_sync(0xffffffffu, d, s);
        float pred = d + bdv;
        float term = fmaxf(pred, 0.f) - pred * y + log1pf(__expf(-fabsf(pred)));
        if (lane == 0) acc += term;
    }
    __shared__ float ws[8];
    if (lane == 0) ws[w] = acc;
    __syncthreads();
    if (t == 0) {
        float s = 0.f;
#pragma unroll
        for (int i = 0; i < 8; i++) s += ws[i];
        atomicAdd(&g_loss, (double)s);
    }
}

// ---------------- K7: finalize ---------------------------------------------
__global__ void k_fin(float* __restrict__ out) {
    out[0] = (float)(g_loss * (1.0 / (double)(2 * EE)));
}

// ---------------- launch ----------------------------------------------------
extern "C" void kernel_launch(void* const* d_in, const int* in_sizes, int n_in,
                              void* d_out, int out_size) {
    const float* x        = (const float*)d_in[0];
    const float* node_ts  = (const float*)d_in[1];
    const int*   nidx     = (const int*)  d_in[2];
    const float* nts      = (const float*)d_in[3];
    const int*   target   = (const int*)  d_in[4];
    const int*   negp     = (const int*)  d_in[5];
    const float* W1       = (const float*)d_in[6];
    // d_in[7] = b1 (cancels in BN)
    const float* g1       = (const float*)d_in[8];
    const float* be1      = (const float*)d_in[9];
    const float* W2       = (const float*)d_in[10];
    // d_in[11] = b2 (cancels in BN)
    const float* g2       = (const float*)d_in[12];
    const float* be2      = (const float*)d_in[13];
    const float* Wd       = (const float*)d_in[14];
    const float* bd       = (const float*)d_in[15];
    float* out = (float*)d_out;

    k_init  <<<1, 256>>>();
    k_xw1   <<<1024, 128>>>(x, W1);
    k_gather<<<2048, 128>>>(node_ts, nidx, nts);
    k_bn1   <<<1, 128>>>(g1, be1);
    k_layer2<<<2048, 128>>>(node_ts, nts, W2);
    k_bn2   <<<1, 64>>>(g2, be2);
    k_dec   <<<2048, 256>>>(target, negp, Wd, bd);
    k_fin   <<<1, 1>>>(out);
}

// round 2
// speedup vs baseline: 1.0697x; 1.0697x over previous
#include <cuda_runtime.h>
#include <cuda_bf16.h>

#define NN   20000
#define DD   8
#define KK   9
#define IN_F 64
#define HID  128
#define OUT  64
#define EE   100000
#define MTOT (NN * KK)
#define EPS  1e-5f

// ---------------- scratch ---------------------------------------------------
__device__ float  g_xW1[NN * HID];                 // x @ W1 (10.24 MB)
__device__ float  g_Qn[(size_t)NN * KK * HID];     // prefix means (92.16 MB)
__device__ float  g_z2[NN * OUT];                  // pre-BN layer-2 (5.12 MB)
__device__ float  g_s1[2 * HID];
__device__ float  g_s2[2 * OUT];
__device__ float  g_bn1[2 * HID];
__device__ float  g_bn2[2 * OUT];
__device__ double g_loss;

// ---------------- K0: zero accumulators ------------------------------------
__global__ void k_init() {
    int t = threadIdx.x;
    if (t < 2 * HID) g_s1[t] = 0.f;
    if (t < 2 * OUT) g_s2[t] = 0.f;
    if (t == 0) g_loss = 0.0;
}

// ---------------- K1: xW1 = x @ W1 ------------------------------------------
__global__ void k_xw1(const float* __restrict__ x, const float* __restrict__ W1) {
    int t = threadIdx.x;            // column j in [0,128)
    float w[IN_F];
#pragma unroll
    for (int i = 0; i < IN_F; i++) w[i] = W1[i * HID + t];

    __shared__ __align__(16) float xs[4 * IN_F];
    for (int r0 = blockIdx.x * 4; r0 < NN; r0 += gridDim.x * 4) {
        __syncthreads();
        for (int i = t; i < 4 * IN_F; i += 128) xs[i] = x[r0 * IN_F + i];
        __syncthreads();
#pragma unroll
        for (int r = 0; r < 4; r++) {
            const float4* a4 = (const float4*)(xs + r * IN_F);
            float acc = 0.f;
#pragma unroll
            for (int ff = 0; ff < 16; ff++) {
                float4 a = a4[ff];
                acc = fmaf(a.x, w[4 * ff + 0], acc);
                acc = fmaf(a.y, w[4 * ff + 1], acc);
                acc = fmaf(a.z, w[4 * ff + 2], acc);
                acc = fmaf(a.w, w[4 * ff + 3], acc);
            }
            g_xW1[(r0 + r) * HID + t] = acc;
        }
    }
}

// ---------------- K2: per-node time-sorted prefix means ---------------------
// Qn[c][k] = (xW1[c] + sum of k smallest-ts neighbors' xW1) / (k+1)
__global__ void k_build(const int* __restrict__ nidx, const float* __restrict__ nts) {
    __shared__ float ts_s[8];
    __shared__ int   id_s[8];
    __shared__ int   ord[8];
    int t = threadIdx.x;            // column j in [0,128)
    for (int c = blockIdx.x; c < NN; c += gridDim.x) {
        __syncthreads();
        if (t < 8) { ts_s[t] = nts[c * 8 + t]; id_s[t] = nidx[c * 8 + t]; }
        __syncthreads();
        if (t < 8) {                 // rank sort (index tiebreak)
            float mine = ts_s[t]; int r = 0;
#pragma unroll
            for (int i = 0; i < 8; i++) {
                float o = ts_s[i];
                r += (o < mine) || (o == mine && i < t);
            }
            ord[r] = t;
        }
        __syncthreads();
        float q = g_xW1[c * HID + t];
        float* qb = g_Qn + (size_t)c * KK * HID + t;
        qb[0] = q;
#pragma unroll
        for (int j = 0; j < 8; j++) {
            q += g_xW1[id_s[ord[j]] * HID + t];
            qb[(j + 1) * HID] = q * (1.0f / (float)(j + 2));
        }
    }
}

// ---------------- K3: BN1 statistics over all M queries ---------------------
#define SI 8
__global__ void k_stats(const float* __restrict__ node_ts,
                        const int*   __restrict__ nidx,
                        const float* __restrict__ nts) {
    __shared__ int off[SI];
    int t = threadIdx.x;
    float ssum = 0.f, ssq = 0.f;
    for (int m0 = blockIdx.x * SI; m0 < MTOT; m0 += gridDim.x * SI) {
        __syncthreads();
        if (t < SI) {
            int m = m0 + t, o = -1;
            if (m < MTOT) {
                int n = m / 9, kc = m - n * 9;
                int ci; float cts;
                if (kc < DD) { ci = nidx[n * DD + kc]; cts = nts[n * DD + kc]; }
                else         { ci = n;                 cts = node_ts[n]; }
                const float4* s4 = (const float4*)(nts + ci * 8);
                float4 a = s4[0], b = s4[1];
                int k = (a.x <= cts) + (a.y <= cts) + (a.z <= cts) + (a.w <= cts)
                      + (b.x <= cts) + (b.y <= cts) + (b.z <= cts) + (b.w <= cts);
                o = ci * KK + k;
            }
            off[t] = o;
        }
        __syncthreads();
#pragma unroll
        for (int r = 0; r < SI; r++) {
            int o = off[r];
            if (o >= 0) {
                float z = g_Qn[(size_t)o * HID + t];
                ssum += z; ssq += z * z;
            }
        }
    }
    atomicAdd(&g_s1[t], ssum);
    atomicAdd(&g_s1[HID + t], ssq);
}

// ---------------- K4: BN1 scale/shift ---------------------------------------
__global__ void k_bn1(const float* __restrict__ g1, const float* __restrict__ be1) {
    int j = threadIdx.x;
    float inv  = 1.0f / (float)MTOT;
    float mean = g_s1[j] * inv;
    float var  = g_s1[HID + j] * inv - mean * mean;
    float sc   = g1[j] * rsqrtf(var + EPS);
    g_bn1[j] = sc;
    g_bn1[HID + j] = be1[j] - mean * sc;
}

// ---------------- K5: BN1+ReLU, level-2 mean, GEMM2 -------------------------
__global__ void k_layer2(const float* __restrict__ node_ts,
                         const int*   __restrict__ nidx,
                         const float* __restrict__ nts,
                         const float* __restrict__ W2) {
    int t = threadIdx.x, o = t & 63, h = t >> 6;
    float w[64];
#pragma unroll
    for (int i = 0; i < 64; i++) w[i] = W2[(h * 64 + i) * OUT + o];

    float sc = g_bn1[t], sh = g_bn1[HID + t];
    __shared__ int off9[KK];
    __shared__ __align__(16) float agg_s[HID];
    __shared__ float bs[HID];
    __shared__ float rcp[16];
    if (t < 16) rcp[t] = (t > 0) ? 1.0f / (float)t : 0.f;

    float s2 = 0.f, q2 = 0.f;
    for (int n = blockIdx.x; n < NN; n += gridDim.x) {
        __syncthreads();
        if (t < KK) {
            float tsn = node_ts[n];
            int ci; float cts; bool valid;
            if (t < DD) { ci = nidx[n * DD + t]; cts = nts[n * DD + t]; valid = (cts <= tsn); }
            else        { ci = n;                cts = tsn;             valid = true; }
            int o2 = -1;
            if (valid) {
                const float4* s4 = (const float4*)(nts + ci * 8);
                float4 a = s4[0], b = s4[1];
                int k = (a.x <= cts) + (a.y <= cts) + (a.z <= cts) + (a.w <= cts)
                      + (b.x <= cts) + (b.y <= cts) + (b.z <= cts) + (b.w <= cts);
                o2 = ci * KK + k;
            }
            off9[t] = o2;
        }
        __syncthreads();
        float acc = 0.f; int cnt = 0;
#pragma unroll
        for (int kc = 0; kc < KK; kc++) {
            int o2 = off9[kc];
            if (o2 >= 0) {
                float z = g_Qn[(size_t)o2 * HID + t];
                acc += fmaxf(fmaf(z, sc, sh), 0.f);
                cnt++;
            }
        }
        agg_s[t] = acc * rcp[cnt];
        __syncthreads();
        float a2 = 0.f;
        const float4* a4 = (const float4*)(agg_s + 64 * h);
#pragma unroll
        for (int ff = 0; ff < 16; ff++) {
            float4 a = a4[ff];
            a2 = fmaf(a.x, w[4 * ff + 0], a2);
            a2 = fmaf(a.y, w[4 * ff + 1], a2);
            a2 = fmaf(a.z, w[4 * ff + 2], a2);
            a2 = fmaf(a.w, w[4 * ff + 3], a2);
        }
        bs[t] = a2;
        __syncthreads();
        if (t < 64) {
            float z2 = bs[t] + bs[t + 64];
            g_z2[n * OUT + t] = z2;
            s2 += z2; q2 += z2 * z2;
        }
    }
    if (t < 64) {
        atomicAdd(&g_s2[t], s2);
        atomicAdd(&g_s2[OUT + t], q2);
    }
}

// ---------------- K6: BN2 scale/shift ---------------------------------------
__global__ void k_bn2(const float* __restrict__ g2, const float* __restrict__ be2) {
    int j = threadIdx.x;
    float inv  = 1.0f / (float)NN;
    float mean = g_s2[j] * inv;
    float var  = g_s2[OUT + j] * inv - mean * mean;
    float sc   = g2[j] * rsqrtf(var + EPS);
    g_bn2[j] = sc;
    g_bn2[OUT + j] = be2[j] - mean * sc;
}

// ---------------- K7: Hadamard decoder + BCE --------------------------------
__global__ void k_dec(const int* __restrict__ target, const int* __restrict__ negp,
                      const float* __restrict__ Wd, const float* __restrict__ bd) {
    int t = threadIdx.x, lane = t & 31, w = t >> 5;
    int gw = blockIdx.x * 8 + w;
    int nw = gridDim.x * 8;

    float sca = g_bn2[lane],      sha = g_bn2[64 + lane];
    float scb = g_bn2[lane + 32], shb = g_bn2[96 + lane];
    float wda = Wd[lane], wdb = Wd[lane + 32];
    float bdv = bd[0];

    float acc = 0.f;
    for (int p = gw; p < 2 * EE; p += nw) {
        int u, v; float y;
        if (p < EE) { u = target[p]; v = target[EE + p]; y = 1.f; }
        else        { u = negp[p - EE]; v = negp[p];     y = 0.f; }
        float eu1 = fmaxf(fmaf(g_z2[u * 64 + lane],      sca, sha), 0.f);
        float ev1 = fmaxf(fmaf(g_z2[v * 64 + lane],      sca, sha), 0.f);
        float eu2 = fmaxf(fmaf(g_z2[u * 64 + 32 + lane], scb, shb), 0.f);
        float ev2 = fmaxf(fmaf(g_z2[v * 64 + 32 + lane], scb, shb), 0.f);
        float d = eu1 * ev1 * wda + eu2 * ev2 * wdb;
#pragma unroll
        for (int s = 16; s > 0; s >>= 1) d += __shfl_xor_sync(0xffffffffu, d, s);
        float pred = d + bdv;
        float term = fmaxf(pred, 0.f) - pred * y + log1pf(__expf(-fabsf(pred)));
        if (lane == 0) acc += term;
    }
    __shared__ float ws[8];
    if (lane == 0) ws[w] = acc;
    __syncthreads();
    if (t == 0) {
        float s = 0.f;
#pragma unroll
        for (int i = 0; i < 8; i++) s += ws[i];
        atomicAdd(&g_loss, (double)s);
    }
}

// ---------------- K8: finalize -----------------------------------------------
__global__ void k_fin(float* __restrict__ out) {
    out[0] = (float)(g_loss * (1.0 / (double)(2 * EE)));
}

// ---------------- launch ------------------------------------------------------
extern "C" void kernel_launch(void* const* d_in, const int* in_sizes, int n_in,
                              void* d_out, int out_size) {
    const float* x        = (const float*)d_in[0];
    const float* node_ts  = (const float*)d_in[1];
    const int*   nidx     = (const int*)  d_in[2];
    const float* nts      = (const float*)d_in[3];
    const int*   target   = (const int*)  d_in[4];
    const int*   negp     = (const int*)  d_in[5];
    const float* W1       = (const float*)d_in[6];
    const float* g1       = (const float*)d_in[8];
    const float* be1      = (const float*)d_in[9];
    const float* W2       = (const float*)d_in[10];
    const float* g2       = (const float*)d_in[12];
    const float* be2      = (const float*)d_in[13];
    const float* Wd       = (const float*)d_in[14];
    const float* bd       = (const float*)d_in[15];
    float* out = (float*)d_out;

    k_init  <<<1, 256>>>();
    k_xw1   <<<1024, 128>>>(x, W1);
    k_build <<<2048, 128>>>(nidx, nts);
    k_stats <<<2048, 128>>>(node_ts, nidx, nts);
    k_bn1   <<<1, 128>>>(g1, be1);
    k_layer2<<<2048, 128>>>(node_ts, nidx, nts, W2);
    k_bn2   <<<1, 64>>>(g2, be2);
    k_dec   <<<2048, 256>>>(target, negp, Wd, bd);
    k_fin   <<<1, 1>>>(out);
}

// round 3
// speedup vs baseline: 1.2235x; 1.1437x over previous
#include <cuda_runtime.h>
#include <cuda_bf16.h>
#include <cuda_fp16.h>

#define NN   20000
#define DD   8
#define KK   9
#define IN_F 64
#define HID  128
#define OUT  64
#define EE   100000
#define MTOT (NN * KK)
#define EPS  1e-5f

// ---------------- scratch ---------------------------------------------------
__device__ float  g_xW1[NN * HID];                 // x @ W1 (10.24 MB)
__device__ __half g_Qh[(size_t)MTOT * HID];        // prefix means, fp16 (46.08 MB)
__device__ int    g_cnt[MTOT];                     // query histogram (720 KB)
__device__ float  g_z2[NN * OUT];                  // pre-BN layer-2 (5.12 MB)
__device__ float  g_s1[2 * HID];
__device__ float  g_s2[2 * OUT];
__device__ float  g_bn1[2 * HID];
__device__ float  g_bn2[2 * OUT];
__device__ double g_loss;

// ---------------- K0: zero accumulators + histogram -------------------------
__global__ void k_init() {
    int g = blockIdx.x * blockDim.x + threadIdx.x;
    for (int i = g; i < MTOT; i += gridDim.x * blockDim.x) g_cnt[i] = 0;
    if (blockIdx.x == 0) {
        int t = threadIdx.x;
        if (t < 2 * HID) g_s1[t] = 0.f;
        if (t < 2 * OUT) g_s2[t] = 0.f;
        if (t == 0) g_loss = 0.0;
    }
}

// ---------------- K1: xW1 = x @ W1 ------------------------------------------
__global__ void k_xw1(const float* __restrict__ x, const float* __restrict__ W1) {
    int t = threadIdx.x;            // column j in [0,128)
    float w[IN_F];
#pragma unroll
    for (int i = 0; i < IN_F; i++) w[i] = W1[i * HID + t];

    __shared__ __align__(16) float xs[4 * IN_F];
    for (int r0 = blockIdx.x * 4; r0 < NN; r0 += gridDim.x * 4) {
        __syncthreads();
        for (int i = t; i < 4 * IN_F; i += 128) xs[i] = x[r0 * IN_F + i];
        __syncthreads();
#pragma unroll
        for (int r = 0; r < 4; r++) {
            const float4* a4 = (const float4*)(xs + r * IN_F);
            float acc = 0.f;
#pragma unroll
            for (int ff = 0; ff < 16; ff++) {
                float4 a = a4[ff];
                acc = fmaf(a.x, w[4 * ff + 0], acc);
                acc = fmaf(a.y, w[4 * ff + 1], acc);
                acc = fmaf(a.z, w[4 * ff + 2], acc);
                acc = fmaf(a.w, w[4 * ff + 3], acc);
            }
            g_xW1[(r0 + r) * HID + t] = acc;
        }
    }
}

// ---------------- K2: query histogram ---------------------------------------
// Each level-1 query m maps to row (ci, k); count multiplicities.
__global__ void k_hist(const float* __restrict__ node_ts,
                       const int*   __restrict__ nidx,
                       const float* __restrict__ nts) {
    int m = blockIdx.x * blockDim.x + threadIdx.x;
    if (m >= MTOT) return;
    int n = m / 9, kc = m - n * 9;
    int ci; float cts;
    if (kc < DD) { ci = nidx[n * DD + kc]; cts = nts[n * DD + kc]; }
    else         { ci = n;                 cts = node_ts[n]; }
    const float4* s4 = (const float4*)(nts + ci * 8);
    float4 a = s4[0], b = s4[1];
    int k = (a.x <= cts) + (a.y <= cts) + (a.z <= cts) + (a.w <= cts)
          + (b.x <= cts) + (b.y <= cts) + (b.z <= cts) + (b.w <= cts);
    atomicAdd(&g_cnt[ci * KK + k], 1);
}

// ---------------- K3: build prefix means + fused BN1 stats -------------------
__global__ void k_build(const int* __restrict__ nidx, const float* __restrict__ nts) {
    __shared__ float ts_s[8];
    __shared__ int   id_s[8];
    __shared__ int   ord[8];
    __shared__ float wc[KK];
    int t = threadIdx.x;            // column j in [0,128)
    float ssum = 0.f, ssq = 0.f;
    for (int c = blockIdx.x; c < NN; c += gridDim.x) {
        __syncthreads();
        if (t < 8) { ts_s[t] = nts[c * 8 + t]; id_s[t] = nidx[c * 8 + t]; }
        if (t >= 32 && t < 32 + KK) wc[t - 32] = (float)g_cnt[c * KK + (t - 32)];
        __syncthreads();
        if (t < 8) {                 // rank sort (index tiebreak)
            float mine = ts_s[t]; int r = 0;
#pragma unroll
            for (int i = 0; i < 8; i++) {
                float o = ts_s[i];
                r += (o < mine) || (o == mine && i < t);
            }
            ord[r] = t;
        }
        __syncthreads();
        float q = g_xW1[c * HID + t];
        __half* qb = g_Qh + (size_t)c * KK * HID + t;
        qb[0] = __float2half_rn(q);
        { float w0 = wc[0]; ssum += w0 * q; ssq += w0 * q * q; }
#pragma unroll
        for (int j = 0; j < 8; j++) {
            q += g_xW1[id_s[ord[j]] * HID + t];
            float qm = q * (1.0f / (float)(j + 2));
            qb[(j + 1) * HID] = __float2half_rn(qm);
            float wj = wc[j + 1];
            ssum += wj * qm; ssq += wj * qm * qm;
        }
    }
    atomicAdd(&g_s1[t], ssum);
    atomicAdd(&g_s1[HID + t], ssq);
}

// ---------------- K4: BN1 scale/shift ---------------------------------------
__global__ void k_bn1(const float* __restrict__ g1, const float* __restrict__ be1) {
    int j = threadIdx.x;
    float inv  = 1.0f / (float)MTOT;
    float mean = g_s1[j] * inv;
    float var  = g_s1[HID + j] * inv - mean * mean;
    float sc   = g1[j] * rsqrtf(var + EPS);
    g_bn1[j] = sc;
    g_bn1[HID + j] = be1[j] - mean * sc;
}

// ---------------- K5: BN1+ReLU, level-2 mean, GEMM2 -------------------------
__global__ void k_layer2(const float* __restrict__ node_ts,
                         const int*   __restrict__ nidx,
                         const float* __restrict__ nts,
                         const float* __restrict__ W2) {
    int t = threadIdx.x, o = t & 63, h = t >> 6;
    float w[64];
#pragma unroll
    for (int i = 0; i < 64; i++) w[i] = W2[(h * 64 + i) * OUT + o];

    float sc = g_bn1[t], sh = g_bn1[HID + t];
    __shared__ int off9[KK];
    __shared__ __align__(16) float agg_s[HID];
    __shared__ float bs[HID];
    __shared__ float rcp[16];
    if (t < 16) rcp[t] = (t > 0) ? 1.0f / (float)t : 0.f;

    float s2 = 0.f, q2 = 0.f;
    for (int n = blockIdx.x; n < NN; n += gridDim.x) {
        __syncthreads();
        if (t < KK) {
            float tsn = node_ts[n];
            int ci; float cts; bool valid;
            if (t < DD) { ci = nidx[n * DD + t]; cts = nts[n * DD + t]; valid = (cts <= tsn); }
            else        { ci = n;                cts = tsn;             valid = true; }
            int o2 = -1;
            if (valid) {
                const float4* s4 = (const float4*)(nts + ci * 8);
                float4 a = s4[0], b = s4[1];
                int k = (a.x <= cts) + (a.y <= cts) + (a.z <= cts) + (a.w <= cts)
                      + (b.x <= cts) + (b.y <= cts) + (b.z <= cts) + (b.w <= cts);
                o2 = ci * KK + k;
            }
            off9[t] = o2;
        }
        __syncthreads();
        float acc = 0.f; int cnt = 0;
#pragma unroll
        for (int kc = 0; kc < KK; kc++) {
            int o2 = off9[kc];
            if (o2 >= 0) {
                float z = __half2float(g_Qh[(size_t)o2 * HID + t]);
                acc += fmaxf(fmaf(z, sc, sh), 0.f);
                cnt++;
            }
        }
        agg_s[t] = acc * rcp[cnt];
        __syncthreads();
        float a2 = 0.f;
        const float4* a4 = (const float4*)(agg_s + 64 * h);
#pragma unroll
        for (int ff = 0; ff < 16; ff++) {
            float4 a = a4[ff];
            a2 = fmaf(a.x, w[4 * ff + 0], a2);
            a2 = fmaf(a.y, w[4 * ff + 1], a2);
            a2 = fmaf(a.z, w[4 * ff + 2], a2);
            a2 = fmaf(a.w, w[4 * ff + 3], a2);
        }
        bs[t] = a2;
        __syncthreads();
        if (t < 64) {
            float z2 = bs[t] + bs[t + 64];
            g_z2[n * OUT + t] = z2;
            s2 += z2; q2 += z2 * z2;
        }
    }
    if (t < 64) {
        atomicAdd(&g_s2[t], s2);
        atomicAdd(&g_s2[OUT + t], q2);
    }
}

// ---------------- K6: BN2 scale/shift ---------------------------------------
__global__ void k_bn2(const float* __restrict__ g2, const float* __restrict__ be2) {
    int j = threadIdx.x;
    float inv  = 1.0f / (float)NN;
    float mean = g_s2[j] * inv;
    float var  = g_s2[OUT + j] * inv - mean * mean;
    float sc   = g2[j] * rsqrtf(var + EPS);
    g_bn2[j] = sc;
    g_bn2[OUT + j] = be2[j] - mean * sc;
}

// ---------------- K7: Hadamard decoder + BCE --------------------------------
__global__ void k_dec(const int* __restrict__ target, const int* __restrict__ negp,
                      const float* __restrict__ Wd, const float* __restrict__ bd) {
    int t = threadIdx.x, lane = t & 31, w = t >> 5;
    int gw = blockIdx.x * 8 + w;
    int nw = gridDim.x * 8;

    float sca = g_bn2[lane],      sha = g_bn2[64 + lane];
    float scb = g_bn2[lane + 32], shb = g_bn2[96 + lane];
    float wda = Wd[lane], wdb = Wd[lane + 32];
    float bdv = bd[0];

    float acc = 0.f;
    for (int p = gw; p < 2 * EE; p += nw) {
        int u, v; float y;
        if (p < EE) { u = target[p]; v = target[EE + p]; y = 1.f; }
        else        { u = negp[p - EE]; v = negp[p];     y = 0.f; }
        float eu1 = fmaxf(fmaf(g_z2[u * 64 + lane],      sca, sha), 0.f);
        float ev1 = fmaxf(fmaf(g_z2[v * 64 + lane],      sca, sha), 0.f);
        float eu2 = fmaxf(fmaf(g_z2[u * 64 + 32 + lane], scb, shb), 0.f);
        float ev2 = fmaxf(fmaf(g_z2[v * 64 + 32 + lane], scb, shb), 0.f);
        float d = eu1 * ev1 * wda + eu2 * ev2 * wdb;
#pragma unroll
        for (int s = 16; s > 0; s >>= 1) d += __shfl_xor_sync(0xffffffffu, d, s);
        float pred = d + bdv;
        float term = fmaxf(pred, 0.f) - pred * y + log1pf(__expf(-fabsf(pred)));
        if (lane == 0) acc += term;
    }
    __shared__ float ws[8];
    if (lane == 0) ws[w] = acc;
    __syncthreads();
    if (t == 0) {
        float s = 0.f;
#pragma unroll
        for (int i = 0; i < 8; i++) s += ws[i];
        atomicAdd(&g_loss, (double)s);
    }
}

// ---------------- K8: finalize -----------------------------------------------
__global__ void k_fin(float* __restrict__ out) {
    out[0] = (float)(g_loss * (1.0 / (double)(2 * EE)));
}

// ---------------- launch ------------------------------------------------------
extern "C" void kernel_launch(void* const* d_in, const int* in_sizes, int n_in,
                              void* d_out, int out_size) {
    const float* x        = (const float*)d_in[0];
    const float* node_ts  = (const float*)d_in[1];
    const int*   nidx     = (const int*)  d_in[2];
    const float* nts      = (const float*)d_in[3];
    const int*   target   = (const int*)  d_in[4];
    const int*   negp     = (const int*)  d_in[5];
    const float* W1       = (const float*)d_in[6];
    const float* g1       = (const float*)d_in[8];
    const float* be1      = (const float*)d_in[9];
    const float* W2       = (const float*)d_in[10];
    const float* g2       = (const float*)d_in[12];
    const float* be2      = (const float*)d_in[13];
    const float* Wd       = (const float*)d_in[14];
    const float* bd       = (const float*)d_in[15];
    float* out = (float*)d_out;

    k_init  <<<512, 256>>>();
    k_xw1   <<<1024, 128>>>(x, W1);
    k_hist  <<<(MTOT + 255) / 256, 256>>>(node_ts, nidx, nts);
    k_build <<<2048, 128>>>(nidx, nts);
    k_bn1   <<<1, 128>>>(g1, be1);
    k_layer2<<<2048, 128>>>(node_ts, nidx, nts, W2);
    k_bn2   <<<1, 64>>>(g2, be2);
    k_dec   <<<2048, 256>>>(target, negp, Wd, bd);
    k_fin   <<<1, 1>>>(out);
}

// round 5
// speedup vs baseline: 1.6925x; 1.3833x over previous
#include <cuda_runtime.h>
#include <cuda_bf16.h>
#include <cuda_fp16.h>

#define NN   20000
#define DD   8
#define KK   9
#define IN_F 64
#define HID  128
#define OUT  64
#define EE   100000
#define MTOT (NN * KK)
#define EPS  1e-5f
#define FULL 0xffffffffu

// ---------------- scratch ---------------------------------------------------
__device__ float  g_xW1[NN * HID];                 // x @ W1 (10.24 MB)
__device__ __half g_Qh[(size_t)MTOT * HID];        // prefix means, fp16 (46.08 MB)
__device__ int    g_cnt[MTOT];                     // query histogram (720 KB)
__device__ float  g_z2[NN * OUT];                  // pre-BN layer-2 (5.12 MB)
__device__ __half g_emb[NN * OUT];                 // post-BN2 embeddings (2.56 MB)
__device__ float  g_s1[2 * HID];
__device__ float  g_s2[2 * OUT];
__device__ float  g_bn1[2 * HID];
__device__ float  g_bn2[2 * OUT];
__device__ double g_loss;

// ---------------- K0: zero accumulators + histogram -------------------------
__global__ void k_init() {
    int g = blockIdx.x * blockDim.x + threadIdx.x;
    for (int i = g; i < MTOT; i += gridDim.x * blockDim.x) g_cnt[i] = 0;
    if (blockIdx.x == 0) {
        int t = threadIdx.x;
        if (t < 2 * HID) g_s1[t] = 0.f;
        if (t < 2 * OUT) g_s2[t] = 0.f;
        if (t == 0) g_loss = 0.0;
    }
}

// ---------------- K1: xW1 = x @ W1 ------------------------------------------
__global__ void k_xw1(const float* __restrict__ x, const float* __restrict__ W1) {
    int t = threadIdx.x;            // column j in [0,128)
    float w[IN_F];
#pragma unroll
    for (int i = 0; i < IN_F; i++) w[i] = W1[i * HID + t];

    __shared__ __align__(16) float xs[4 * IN_F];
    for (int r0 = blockIdx.x * 4; r0 < NN; r0 += gridDim.x * 4) {
        __syncthreads();
        for (int i = t; i < 4 * IN_F; i += 128) xs[i] = x[r0 * IN_F + i];
        __syncthreads();
#pragma unroll
        for (int r = 0; r < 4; r++) {
            const float4* a4 = (const float4*)(xs + r * IN_F);
            float acc = 0.f;
#pragma unroll
            for (int ff = 0; ff < 16; ff++) {
                float4 a = a4[ff];
                acc = fmaf(a.x, w[4 * ff + 0], acc);
                acc = fmaf(a.y, w[4 * ff + 1], acc);
                acc = fmaf(a.z, w[4 * ff + 2], acc);
                acc = fmaf(a.w, w[4 * ff + 3], acc);
            }
            g_xW1[(r0 + r) * HID + t] = acc;
        }
    }
}

// ---------------- K2: query histogram ---------------------------------------
__global__ void k_hist(const float* __restrict__ node_ts,
                       const int*   __restrict__ nidx,
                       const float* __restrict__ nts) {
    int m = blockIdx.x * blockDim.x + threadIdx.x;
    if (m >= MTOT) return;
    int n = m / 9, kc = m - n * 9;
    int ci; float cts;
    if (kc < DD) { ci = nidx[n * DD + kc]; cts = nts[n * DD + kc]; }
    else         { ci = n;                 cts = node_ts[n]; }
    const float4* s4 = (const float4*)(nts + ci * 8);
    float4 a = s4[0], b = s4[1];
    int k = (a.x <= cts) + (a.y <= cts) + (a.z <= cts) + (a.w <= cts)
          + (b.x <= cts) + (b.y <= cts) + (b.z <= cts) + (b.w <= cts);
    atomicAdd(&g_cnt[ci * KK + k], 1);
}

// ---------------- K3: warp-per-node prefix means + fused BN1 stats ----------
__global__ void k_build(const int* __restrict__ nidx, const float* __restrict__ nts) {
    int lane = threadIdx.x & 31, w = threadIdx.x >> 5;
    int wid = blockIdx.x * (blockDim.x >> 5) + w;
    int nw  = gridDim.x * (blockDim.x >> 5);

    float s0=0,s1=0,s2=0,s3=0, p0=0,p1=0,p2=0,p3=0;

    for (int c = wid; c < NN; c += nw) {
        float ts = 1e30f; int id = 0;
        if (lane < 8) { ts = nts[c * 8 + lane]; id = nidx[c * 8 + lane]; }
        int r = 0;
#pragma unroll
        for (int i = 0; i < 8; i++) {
            float o = __shfl_sync(FULL, ts, i);
            r += (o < ts) || (o == ts && i < lane);
        }
        int ids[8];
#pragma unroll
        for (int j = 0; j < 8; j++) {
            unsigned b = __ballot_sync(FULL, (lane < 8) && (r == j));
            int src = __ffs(b) - 1;
            ids[j] = __shfl_sync(FULL, id, src);
        }
        float wcl = (lane < 9) ? (float)g_cnt[c * KK + lane] : 0.f;

        float4 q = ((const float4*)(g_xW1 + (size_t)c * HID))[lane];
        float4 nb[8];
#pragma unroll
        for (int j = 0; j < 8; j++)
            nb[j] = ((const float4*)(g_xW1 + (size_t)ids[j] * HID))[lane];

        uint2* qb = (uint2*)(g_Qh + (size_t)c * KK * HID) + lane;  // row stride 32 uint2
        union { __half2 h[2]; uint2 u; } pk;

        float w0 = __shfl_sync(FULL, wcl, 0);
        pk.h[0] = __floats2half2_rn(q.x, q.y);
        pk.h[1] = __floats2half2_rn(q.z, q.w);
        qb[0] = pk.u;
        s0 += w0*q.x; p0 += w0*q.x*q.x;
        s1 += w0*q.y; p1 += w0*q.y*q.y;
        s2 += w0*q.z; p2 += w0*q.z*q.z;
        s3 += w0*q.w; p3 += w0*q.w*q.w;
#pragma unroll
        for (int j = 0; j < 8; j++) {
            q.x += nb[j].x; q.y += nb[j].y; q.z += nb[j].z; q.w += nb[j].w;
            float inv = 1.0f / (float)(j + 2);
            float mx = q.x*inv, my = q.y*inv, mz = q.z*inv, mw = q.w*inv;
            pk.h[0] = __floats2half2_rn(mx, my);
            pk.h[1] = __floats2half2_rn(mz, mw);
            qb[(j + 1) * 32] = pk.u;
            float wj = __shfl_sync(FULL, wcl, j + 1);
            s0 += wj*mx; p0 += wj*mx*mx;
            s1 += wj*my; p1 += wj*my*my;
            s2 += wj*mz; p2 += wj*mz*mz;
            s3 += wj*mw; p3 += wj*mw*mw;
        }
    }
    __shared__ float red[2 * HID];
    int t = threadIdx.x;
    if (t < 2 * HID) red[t] = 0.f;
    __syncthreads();
    atomicAdd(&red[4*lane + 0], s0); atomicAdd(&red[HID + 4*lane + 0], p0);
    atomicAdd(&red[4*lane + 1], s1); atomicAdd(&red[HID + 4*lane + 1], p1);
    atomicAdd(&red[4*lane + 2], s2); atomicAdd(&red[HID + 4*lane + 2], p2);
    atomicAdd(&red[4*lane + 3], s3); atomicAdd(&red[HID + 4*lane + 3], p3);
    __syncthreads();
    if (t < 2 * HID) atomicAdd(&g_s1[t], red[t]);
}

// ---------------- K4: BN1 scale/shift ---------------------------------------
__global__ void k_bn1(const float* __restrict__ g1, const float* __restrict__ be1) {
    int j = threadIdx.x;
    float inv  = 1.0f / (float)MTOT;
    float mean = g_s1[j] * inv;
    float var  = g_s1[HID + j] * inv - mean * mean;
    float sc   = g1[j] * rsqrtf(var + EPS);
    g_bn1[j] = sc;
    g_bn1[HID + j] = be1[j] - mean * sc;
}

// ---------------- K5: BN1+ReLU, level-2 mean, GEMM2 (2 nodes/iter) ----------
__global__ void k_layer2(const float* __restrict__ node_ts,
                         const int*   __restrict__ nidx,
                         const float* __restrict__ nts,
                         const float* __restrict__ W2) {
    int t = threadIdx.x, o = t & 63, h = t >> 6;   // GEMM role
    int cp = t & 63, a = t >> 6;                   // gather role: node a, cols 2cp,2cp+1
    float w[64];
#pragma unroll
    for (int i = 0; i < 64; i++) w[i] = W2[(h * 64 + i) * OUT + o];

    float2 scv = *(const float2*)(g_bn1 + 2 * cp);
    float2 shv = *(const float2*)(g_bn1 + HID + 2 * cp);

    __shared__ int off[2][KK];
    __shared__ __align__(16) float agg[2][HID];
    __shared__ float bs[2][HID];

    float ssum = 0.f, ssq = 0.f;
    for (int n0 = blockIdx.x * 2; n0 < NN; n0 += gridDim.x * 2) {
        __syncthreads();
        if (cp < KK) {
            int n = n0 + a;
            float tsn = node_ts[n];
            int ci; float cts; bool valid;
            if (cp < DD) { ci = nidx[n * DD + cp]; cts = nts[n * DD + cp]; valid = (cts <= tsn); }
            else         { ci = n;                 cts = tsn;              valid = true; }
            int o2 = -1;
            if (valid) {
                const float4* s4 = (const float4*)(nts + ci * 8);
                float4 aa = s4[0], bb = s4[1];
                int k = (aa.x <= cts) + (aa.y <= cts) + (aa.z <= cts) + (aa.w <= cts)
                      + (bb.x <= cts) + (bb.y <= cts) + (bb.z <= cts) + (bb.w <= cts);
                o2 = ci * KK + k;
            }
            off[a][cp] = o2;
        }
        __syncthreads();
        {
            float accx = 0.f, accy = 0.f; int cnt = 0;
#pragma unroll
            for (int kc = 0; kc < KK; kc++) {
                int o2 = off[a][kc];
                if (o2 >= 0) {
                    __half2 zh = ((const __half2*)(g_Qh + (size_t)o2 * HID))[cp];
                    float2 z = __half22float2(zh);
                    accx += fmaxf(fmaf(z.x, scv.x, shv.x), 0.f);
                    accy += fmaxf(fmaf(z.y, scv.y, shv.y), 0.f);
                    cnt++;
                }
            }
            float rc = 1.0f / (float)cnt;
            agg[a][2 * cp]     = accx * rc;
            agg[a][2 * cp + 1] = accy * rc;
        }
        __syncthreads();
#pragma unroll
        for (int g = 0; g < 2; g++) {
            float a2 = 0.f;
            const float4* a4 = (const float4*)(agg[g] + 64 * h);
#pragma unroll
            for (int ff = 0; ff < 16; ff++) {
                float4 av = a4[ff];
                a2 = fmaf(av.x, w[4 * ff + 0], a2);
                a2 = fmaf(av.y, w[4 * ff + 1], a2);
                a2 = fmaf(av.z, w[4 * ff + 2], a2);
                a2 = fmaf(av.w, w[4 * ff + 3], a2);
            }
            bs[g][o + 64 * h] = a2;
        }
        __syncthreads();
        {
            int g = t >> 6, oo = t & 63;
            float z2 = bs[g][oo] + bs[g][oo + 64];
            g_z2[(n0 + g) * OUT + oo] = z2;
            ssum += z2; ssq += z2 * z2;
        }
    }
    atomicAdd(&g_s2[t & 63], ssum);
    atomicAdd(&g_s2[OUT + (t & 63)], ssq);
}

// ---------------- K6: BN2 scale/shift ---------------------------------------
__global__ void k_bn2(const float* __restrict__ g2, const float* __restrict__ be2) {
    int j = threadIdx.x;
    float inv  = 1.0f / (float)NN;
    float mean = g_s2[j] * inv;
    float var  = g_s2[OUT + j] * inv - mean * mean;
    float sc   = g2[j] * rsqrtf(var + EPS);
    g_bn2[j] = sc;
    g_bn2[OUT + j] = be2[j] - mean * sc;
}

// ---------------- K7: embeddings = relu(BN2(z2)) as fp16 --------------------
__global__ void k_embs() {
    int g = blockIdx.x * blockDim.x + threadIdx.x;   // one half2 (2 cols)
    if (g >= NN * 32) return;
    int n = g >> 5, cp = g & 31;
    float2 z = *(const float2*)(g_z2 + n * OUT + 2 * cp);
    float2 sc = *(const float2*)(g_bn2 + 2 * cp);
    float2 sh = *(const float2*)(g_bn2 + OUT + 2 * cp);
    float ex = fmaxf(fmaf(z.x, sc.x, sh.x), 0.f);
    float ey = fmaxf(fmaf(z.y, sc.y, sh.y), 0.f);
    ((__half2*)g_emb)[g] = __floats2half2_rn(ex, ey);
}

// ---------------- K8: Hadamard decoder + BCE --------------------------------
__global__ void k_dec(const int* __restrict__ target, const int* __restrict__ negp,
                      const float* __restrict__ Wd, const float* __restrict__ bd) {
    int t = threadIdx.x, lane = t & 31, w = t >> 5;
    int gw = blockIdx.x * 8 + w;
    int nw = gridDim.x * 8;

    float2 wd = *(const float2*)(Wd + 2 * lane);
    float bdv = bd[0];

    float acc = 0.f;
    for (int p = gw; p < 2 * EE; p += nw) {
        int u, v; float y;
        if (p < EE) { u = target[p]; v = target[EE + p]; y = 1.f; }
        else        { u = negp[p - EE]; v = negp[p];     y = 0.f; }
        float2 eu = __half22float2(((const __half2*)g_emb)[u * 32 + lane]);
        float2 ev = __half22float2(((const __half2*)g_emb)[v * 32 + lane]);
        float d = eu.x * ev.x * wd.x + eu.y * ev.y * wd.y;
#pragma unroll
        for (int s = 16; s > 0; s >>= 1) d += __shfl_xor_sync(FULL, d, s);
        float pred = d + bdv;
        float term = fmaxf(pred, 0.f) - pred * y + log1pf(__expf(-fabsf(pred)));
        if (lane == 0) acc += term;
    }
    __shared__ float ws[8];
    if (lane == 0) ws[w] = acc;
    __syncthreads();
    if (t == 0) {
        float s = 0.f;
#pragma unroll
        for (int i = 0; i < 8; i++) s += ws[i];
        atomicAdd(&g_loss, (double)s);
    }
}

// ---------------- K9: finalize -----------------------------------------------
__global__ void k_fin(float* __restrict__ out) {
    out[0] = (float)(g_loss * (1.0 / (double)(2 * EE)));
}

// ---------------- launch ------------------------------------------------------
extern "C" void kernel_launch(void* const* d_in, const int* in_sizes, int n_in,
                              void* d_out, int out_size) {
    const float* x        = (const float*)d_in[0];
    const float* node_ts  = (const float*)d_in[1];
    const int*   nidx     = (const int*)  d_in[2];
    const float* nts      = (const float*)d_in[3];
    const int*   target   = (const int*)  d_in[4];
    const int*   negp     = (const int*)  d_in[5];
    const float* W1       = (const float*)d_in[6];
    const float* g1       = (const float*)d_in[8];
    const float* be1      = (const float*)d_in[9];
    const float* W2       = (const float*)d_in[10];
    const float* g2       = (const float*)d_in[12];
    const float* be2      = (const float*)d_in[13];
    const float* Wd       = (const float*)d_in[14];
    const float* bd       = (const float*)d_in[15];
    float* out = (float*)d_out;

    k_init  <<<512, 256>>>();
    k_xw1   <<<1024, 128>>>(x, W1);
    k_hist  <<<(MTOT + 255) / 256, 256>>>(node_ts, nidx, nts);
    k_build <<<512, 256>>>(nidx, nts);
    k_bn1   <<<1, 128>>>(g1, be1);
    k_layer2<<<1024, 128>>>(node_ts, nidx, nts, W2);
    k_bn2   <<<1, 64>>>(g2, be2);
    k_embs  <<<(NN * 32 + 255) / 256, 256>>>();
    k_dec   <<<2048, 256>>>(target, negp, Wd, bd);
    k_fin   <<<1, 1>>>(out);
}

// round 6
// speedup vs baseline: 1.8034x; 1.0655x over previous
#include <cuda_runtime.h>
#include <cuda_bf16.h>
#include <cuda_fp16.h>

#define NN   20000
#define DD   8
#define KK   9
#define IN_F 64
#define HID  128
#define OUT  64
#define EE   100000
#define MTOT (NN * KK)
#define EPS  1e-5f
#define FULL 0xffffffffu

// ---------------- scratch ---------------------------------------------------
__device__ float  g_xW1[NN * HID];                 // x @ W1 (10.24 MB)
__device__ __half g_Qh[(size_t)MTOT * HID];        // prefix means, fp16 (46.08 MB)
__device__ int    g_cnt[MTOT];                     // query histogram (720 KB)
__device__ float  g_z2[NN * OUT];                  // pre-BN layer-2 (5.12 MB)
__device__ __half g_emb[NN * OUT];                 // post-BN2 embeddings (2.56 MB)
__device__ float  g_s1[2 * HID];
__device__ float  g_s2[2 * OUT];
__device__ double g_loss;

// ---------------- K0: zero accumulators + histogram -------------------------
__global__ void k_init() {
    int g = blockIdx.x * blockDim.x + threadIdx.x;
    for (int i = g; i < MTOT; i += gridDim.x * blockDim.x) g_cnt[i] = 0;
    if (blockIdx.x == 0) {
        int t = threadIdx.x;
        if (t < 2 * HID) g_s1[t] = 0.f;
        if (t < 2 * OUT) g_s2[t] = 0.f;
        if (t == 0) g_loss = 0.0;
    }
}

// ---------------- K1: xW1 = x @ W1 ------------------------------------------
__global__ void k_xw1(const float* __restrict__ x, const float* __restrict__ W1) {
    int t = threadIdx.x;            // column j in [0,128)
    float w[IN_F];
#pragma unroll
    for (int i = 0; i < IN_F; i++) w[i] = W1[i * HID + t];

    __shared__ __align__(16) float xs[4 * IN_F];
    for (int r0 = blockIdx.x * 4; r0 < NN; r0 += gridDim.x * 4) {
        __syncthreads();
        for (int i = t; i < 4 * IN_F; i += 128) xs[i] = x[r0 * IN_F + i];
        __syncthreads();
#pragma unroll
        for (int r = 0; r < 4; r++) {
            const float4* a4 = (const float4*)(xs + r * IN_F);
            float acc = 0.f;
#pragma unroll
            for (int ff = 0; ff < 16; ff++) {
                float4 a = a4[ff];
                acc = fmaf(a.x, w[4 * ff + 0], acc);
                acc = fmaf(a.y, w[4 * ff + 1], acc);
                acc = fmaf(a.z, w[4 * ff + 2], acc);
                acc = fmaf(a.w, w[4 * ff + 3], acc);
            }
            g_xW1[(r0 + r) * HID + t] = acc;
        }
    }
}

// ---------------- K2: query histogram ---------------------------------------
__global__ void k_hist(const float* __restrict__ node_ts,
                       const int*   __restrict__ nidx,
                       const float* __restrict__ nts) {
    int m = blockIdx.x * blockDim.x + threadIdx.x;
    if (m >= MTOT) return;
    int n = m / 9, kc = m - n * 9;
    int ci; float cts;
    if (kc < DD) { ci = nidx[n * DD + kc]; cts = nts[n * DD + kc]; }
    else         { ci = n;                 cts = node_ts[n]; }
    const float4* s4 = (const float4*)(nts + ci * 8);
    float4 a = s4[0], b = s4[1];
    int k = (a.x <= cts) + (a.y <= cts) + (a.z <= cts) + (a.w <= cts)
          + (b.x <= cts) + (b.y <= cts) + (b.z <= cts) + (b.w <= cts);
    atomicAdd(&g_cnt[ci * KK + k], 1);
}

// ---------------- K3: warp-per-node prefix means + fused BN1 stats ----------
__global__ void k_build(const int* __restrict__ nidx, const float* __restrict__ nts) {
    int lane = threadIdx.x & 31, w = threadIdx.x >> 5;
    int wid = blockIdx.x * (blockDim.x >> 5) + w;
    int nw  = gridDim.x * (blockDim.x >> 5);

    float s0=0,s1=0,s2=0,s3=0, p0=0,p1=0,p2=0,p3=0;

    for (int c = wid; c < NN; c += nw) {
        float ts = 1e30f; int id = 0;
        if (lane < 8) { ts = nts[c * 8 + lane]; id = nidx[c * 8 + lane]; }
        int r = 0;
#pragma unroll
        for (int i = 0; i < 8; i++) {
            float o = __shfl_sync(FULL, ts, i);
            r += (o < ts) || (o == ts && i < lane);
        }
        int ids[8];
#pragma unroll
        for (int j = 0; j < 8; j++) {
            unsigned b = __ballot_sync(FULL, (lane < 8) && (r == j));
            int src = __ffs(b) - 1;
            ids[j] = __shfl_sync(FULL, id, src);
        }
        float wcl = (lane < 9) ? (float)g_cnt[c * KK + lane] : 0.f;
        float wj[9];
#pragma unroll
        for (int j = 0; j < 9; j++) wj[j] = __shfl_sync(FULL, wcl, j);

        float4 q = ((const float4*)(g_xW1 + (size_t)c * HID))[lane];
        float4 nb[8];
#pragma unroll
        for (int j = 0; j < 8; j++)
            nb[j] = ((const float4*)(g_xW1 + (size_t)ids[j] * HID))[lane];

        uint2* qb = (uint2*)(g_Qh + (size_t)c * KK * HID) + lane;  // row stride 32 uint2
        union { __half2 h[2]; uint2 u; } pk;

        if (wj[0] != 0.f) {
            pk.h[0] = __floats2half2_rn(q.x, q.y);
            pk.h[1] = __floats2half2_rn(q.z, q.w);
            qb[0] = pk.u;
            float w0 = wj[0];
            s0 += w0*q.x; p0 += w0*q.x*q.x;
            s1 += w0*q.y; p1 += w0*q.y*q.y;
            s2 += w0*q.z; p2 += w0*q.z*q.z;
            s3 += w0*q.w; p3 += w0*q.w*q.w;
        }
#pragma unroll
        for (int j = 0; j < 8; j++) {
            q.x += nb[j].x; q.y += nb[j].y; q.z += nb[j].z; q.w += nb[j].w;
            float wv = wj[j + 1];
            if (wv != 0.f) {
                float inv = 1.0f / (float)(j + 2);
                float mx = q.x*inv, my = q.y*inv, mz = q.z*inv, mw = q.w*inv;
                pk.h[0] = __floats2half2_rn(mx, my);
                pk.h[1] = __floats2half2_rn(mz, mw);
                qb[(j + 1) * 32] = pk.u;
                s0 += wv*mx; p0 += wv*mx*mx;
                s1 += wv*my; p1 += wv*my*my;
                s2 += wv*mz; p2 += wv*mz*mz;
                s3 += wv*mw; p3 += wv*mw*mw;
            }
        }
    }
    __shared__ float red[2 * HID];
    int t = threadIdx.x;
    if (t < 2 * HID) red[t] = 0.f;
    __syncthreads();
    atomicAdd(&red[4*lane + 0], s0); atomicAdd(&red[HID + 4*lane + 0], p0);
    atomicAdd(&red[4*lane + 1], s1); atomicAdd(&red[HID + 4*lane + 1], p1);
    atomicAdd(&red[4*lane + 2], s2); atomicAdd(&red[HID + 4*lane + 2], p2);
    atomicAdd(&red[4*lane + 3], s3); atomicAdd(&red[HID + 4*lane + 3], p3);
    __syncthreads();
    if (t < 2 * HID) atomicAdd(&g_s1[t], red[t]);
}

// ---------------- K4: BN1(inline)+ReLU, level-2 mean, GEMM2 (4 nodes/iter) --
__global__ void k_layer2(const float* __restrict__ node_ts,
                         const int*   __restrict__ nidx,
                         const float* __restrict__ nts,
                         const float* __restrict__ W2,
                         const float* __restrict__ g1,
                         const float* __restrict__ be1) {
    int t = threadIdx.x;                     // 256 threads
    int o = t & 63, h = (t >> 6) & 1, gsel = t >> 7;   // GEMM role
    int cp = t & 63, a = t >> 6;                        // gather role
    float w[64];
#pragma unroll
    for (int i = 0; i < 64; i++) w[i] = W2[(h * 64 + i) * OUT + o];

    // BN1 params for cols 2cp, 2cp+1 (computed from raw sums; kills k_bn1)
    float2 scv, shv;
    {
        float inv = 1.0f / (float)MTOT;
        int j0 = 2 * cp, j1 = 2 * cp + 1;
        float m0 = g_s1[j0] * inv, m1 = g_s1[j1] * inv;
        float v0 = g_s1[HID + j0] * inv - m0 * m0;
        float v1 = g_s1[HID + j1] * inv - m1 * m1;
        scv.x = g1[j0] * rsqrtf(v0 + EPS);
        scv.y = g1[j1] * rsqrtf(v1 + EPS);
        shv.x = be1[j0] - m0 * scv.x;
        shv.y = be1[j1] - m1 * scv.y;
    }

    __shared__ int off[4][KK];
    __shared__ __align__(16) float agg[4][HID];
    __shared__ float bs[4][HID];

    float ssum = 0.f, ssq = 0.f;
    for (int n0 = blockIdx.x * 4; n0 < NN; n0 += gridDim.x * 4) {
        __syncthreads();
        if (cp < KK) {
            int n = n0 + a;
            float tsn = node_ts[n];
            int ci; float cts; bool valid;
            if (cp < DD) { ci = nidx[n * DD + cp]; cts = nts[n * DD + cp]; valid = (cts <= tsn); }
            else         { ci = n;                 cts = tsn;              valid = true; }
            int o2 = -1;
            if (valid) {
                const float4* s4 = (const float4*)(nts + ci * 8);
                float4 aa = s4[0], bb = s4[1];
                int k = (aa.x <= cts) + (aa.y <= cts) + (aa.z <= cts) + (aa.w <= cts)
                      + (bb.x <= cts) + (bb.y <= cts) + (bb.z <= cts) + (bb.w <= cts);
                o2 = ci * KK + k;
            }
            off[a][cp] = o2;
        }
        __syncthreads();
        {
            float accx = 0.f, accy = 0.f; int cnt = 0;
#pragma unroll
            for (int kc = 0; kc < KK; kc++) {
                int o2 = off[a][kc];
                if (o2 >= 0) {
                    __half2 zh = ((const __half2*)(g_Qh + (size_t)o2 * HID))[cp];
                    float2 z = __half22float2(zh);
                    accx += fmaxf(fmaf(z.x, scv.x, shv.x), 0.f);
                    accy += fmaxf(fmaf(z.y, scv.y, shv.y), 0.f);
                    cnt++;
                }
            }
            float rc = 1.0f / (float)cnt;
            agg[a][2 * cp]     = accx * rc;
            agg[a][2 * cp + 1] = accy * rc;
        }
        __syncthreads();
#pragma unroll
        for (int gi = 0; gi < 2; gi++) {
            int g = 2 * gsel + gi;
            float a2 = 0.f;
            const float4* a4 = (const float4*)(agg[g] + 64 * h);
#pragma unroll
            for (int ff = 0; ff < 16; ff++) {
                float4 av = a4[ff];
                a2 = fmaf(av.x, w[4 * ff + 0], a2);
                a2 = fmaf(av.y, w[4 * ff + 1], a2);
                a2 = fmaf(av.z, w[4 * ff + 2], a2);
                a2 = fmaf(av.w, w[4 * ff + 3], a2);
            }
            bs[g][o + 64 * h] = a2;
        }
        __syncthreads();
        {
            int g = t >> 6, oo = t & 63;
            float z2 = bs[g][oo] + bs[g][oo + 64];
            g_z2[(n0 + g) * OUT + oo] = z2;
            ssum += z2; ssq += z2 * z2;
        }
    }
    atomicAdd(&g_s2[t & 63], ssum);
    atomicAdd(&g_s2[OUT + (t & 63)], ssq);
}

// ---------------- K5: embeddings = relu(BN2(z2)) as fp16 (BN2 inline) -------
__global__ void k_embs(const float* __restrict__ g2, const float* __restrict__ be2) {
    int g = blockIdx.x * blockDim.x + threadIdx.x;   // one half2 (2 cols)
    if (g >= NN * 32) return;
    int n = g >> 5, cp = g & 31;
    int j0 = 2 * cp, j1 = 2 * cp + 1;
    float inv = 1.0f / (float)NN;
    float m0 = g_s2[j0] * inv, m1 = g_s2[j1] * inv;
    float v0 = g_s2[OUT + j0] * inv - m0 * m0;
    float v1 = g_s2[OUT + j1] * inv - m1 * m1;
    float sc0 = g2[j0] * rsqrtf(v0 + EPS);
    float sc1 = g2[j1] * rsqrtf(v1 + EPS);
    float sh0 = be2[j0] - m0 * sc0;
    float sh1 = be2[j1] - m1 * sc1;
    float2 z = *(const float2*)(g_z2 + n * OUT + j0);
    float ex = fmaxf(fmaf(z.x, sc0, sh0), 0.f);
    float ey = fmaxf(fmaf(z.y, sc1, sh1), 0.f);
    ((__half2*)g_emb)[g] = __floats2half2_rn(ex, ey);
}

// ---------------- K6: Hadamard decoder + BCE (4 pairs/warp-iter) ------------
__global__ void k_dec(const int* __restrict__ target, const int* __restrict__ negp,
                      const float* __restrict__ Wd, const float* __restrict__ bd) {
    int t = threadIdx.x, lane = t & 31, w = t >> 5;
    int gw = blockIdx.x * 8 + w;
    int nw = gridDim.x * 8;

    float2 wd = *(const float2*)(Wd + 2 * lane);
    float bdv = bd[0];

    float acc = 0.f;
    for (int base = gw * 4; base < 2 * EE; base += nw * 4) {
        // EE % 4 == 0 and base % 4 == 0 => chunk is purely pos or purely neg
        float y; const int* src; int off0;
        if (base < EE) { src = target; off0 = base;      y = 1.f; }
        else           { src = negp;   off0 = base - EE; y = 0.f; }
        int u0 = src[off0 + 0], u1 = src[off0 + 1], u2 = src[off0 + 2], u3 = src[off0 + 3];
        int v0 = src[EE + off0 + 0], v1 = src[EE + off0 + 1],
            v2 = src[EE + off0 + 2], v3 = src[EE + off0 + 3];
        const __half2* eb = (const __half2*)g_emb;
        __half2 a0 = eb[u0 * 32 + lane], b0 = eb[v0 * 32 + lane];
        __half2 a1 = eb[u1 * 32 + lane], b1 = eb[v1 * 32 + lane];
        __half2 a2 = eb[u2 * 32 + lane], b2 = eb[v2 * 32 + lane];
        __half2 a3 = eb[u3 * 32 + lane], b3 = eb[v3 * 32 + lane];
        float2 fa, fb;
        fa = __half22float2(a0); fb = __half22float2(b0);
        float d0 = fa.x * fb.x * wd.x + fa.y * fb.y * wd.y;
        fa = __half22float2(a1); fb = __half22float2(b1);
        float d1 = fa.x * fb.x * wd.x + fa.y * fb.y * wd.y;
        fa = __half22float2(a2); fb = __half22float2(b2);
        float d2 = fa.x * fb.x * wd.x + fa.y * fb.y * wd.y;
        fa = __half22float2(a3); fb = __half22float2(b3);
        float d3 = fa.x * fb.x * wd.x + fa.y * fb.y * wd.y;
#pragma unroll
        for (int s = 16; s > 0; s >>= 1) {
            d0 += __shfl_xor_sync(FULL, d0, s);
            d1 += __shfl_xor_sync(FULL, d1, s);
            d2 += __shfl_xor_sync(FULL, d2, s);
            d3 += __shfl_xor_sync(FULL, d3, s);
        }
        if (lane == 0) {
            float p0 = d0 + bdv, p1 = d1 + bdv, p2 = d2 + bdv, p3 = d3 + bdv;
            acc += fmaxf(p0, 0.f) - p0 * y + log1pf(__expf(-fabsf(p0)));
            acc += fmaxf(p1, 0.f) - p1 * y + log1pf(__expf(-fabsf(p1)));
            acc += fmaxf(p2, 0.f) - p2 * y + log1pf(__expf(-fabsf(p2)));
            acc += fmaxf(p3, 0.f) - p3 * y + log1pf(__expf(-fabsf(p3)));
        }
    }
    __shared__ float ws[8];
    if (lane == 0) ws[w] = acc;
    __syncthreads();
    if (t == 0) {
        float s = 0.f;
#pragma unroll
        for (int i = 0; i < 8; i++) s += ws[i];
        atomicAdd(&g_loss, (double)s);
    }
}

// ---------------- K7: finalize -----------------------------------------------
__global__ void k_fin(float* __restrict__ out) {
    out[0] = (float)(g_loss * (1.0 / (double)(2 * EE)));
}

// ---------------- launch ------------------------------------------------------
extern "C" void kernel_launch(void* const* d_in, const int* in_sizes, int n_in,
                              void* d_out, int out_size) {
    const float* x        = (const float*)d_in[0];
    const float* node_ts  = (const float*)d_in[1];
    const int*   nidx     = (const int*)  d_in[2];
    const float* nts      = (const float*)d_in[3];
    const int*   target   = (const int*)  d_in[4];
    const int*   negp     = (const int*)  d_in[5];
    const float* W1       = (const float*)d_in[6];
    const float* g1       = (const float*)d_in[8];
    const float* be1      = (const float*)d_in[9];
    const float* W2       = (const float*)d_in[10];
    const float* g2       = (const float*)d_in[12];
    const float* be2      = (const float*)d_in[13];
    const float* Wd       = (const float*)d_in[14];
    const float* bd       = (const float*)d_in[15];
    float* out = (float*)d_out;

    k_init  <<<512, 256>>>();
    k_xw1   <<<1024, 128>>>(x, W1);
    k_hist  <<<(MTOT + 255) / 256, 256>>>(node_ts, nidx, nts);
    k_build <<<512, 256>>>(nidx, nts);
    k_layer2<<<1024, 256>>>(node_ts, nidx, nts, W2, g1, be1);
    k_embs  <<<(NN * 32 + 255) / 256, 256>>>(g2, be2);
    k_dec   <<<2048, 256>>>(target, negp, Wd, bd);
    k_fin   <<<1, 1>>>(out);
}